// round 16
// baseline (speedup 1.0000x reference)
#include <cuda_runtime.h>

#define NUM_G 4096
#define D4    32          // 128 floats = 32 float4 per row
#define DHID  128
#define TPB   512
#define RG    16          // row groups in pass 1 (TPB / 32)
#define EPSV  1e-5f

// Sorted-batch accessor with sentinels: val(-1) = -1, val(n) = NUM_G.
// Element i lives at 32-bit word (i << sh): sh=1 for int64 (LE low word).
__device__ __forceinline__ int valat(const int* __restrict__ b32, int sh, int n, int i)
{
    if (i < 0) return -1;
    if (i >= n) return NUM_G;
    return b32[i << sh];
}

// Warp-cooperative lower_bound(t) seeded at the statistical estimate
// t*n/NUM_G. Exponential expansion guarantees a correct bracket for ANY
// sorted input; typical case is 0 expansions (boundary within +-1024).
// Then 32-ary ballot descent (inclusive invariant: r in [lo, lo+len]).
__device__ int warp_lb_est(const int* __restrict__ b32, int sh, int n,
                           int t, int lane)
{
    int est = (int)(((long long)t * n) >> 12);   // n / NUM_G scaled
    int lo = est - 1024, hi = est + 1024;
    int W = 2048;
    while (true) {
        if (valat(b32, sh, n, lo - 1) >= t) { hi = lo; lo -= W; W <<= 1; continue; }
        if (valat(b32, sh, n, hi - 1) <  t) { lo = hi; hi += W; W <<= 1; continue; }
        break;   // val(lo-1) < t <= "val(hi-1 or sentinel)" => r in [lo, hi]
    }
    if (lo < 0) lo = 0;
    if (hi > n) hi = n;

    int len = hi - lo;                 // r in [lo, lo+len] (inclusive)
    while (len > 32) {
        int chunk = (len + 31) >> 5;
        int pos = lo + lane * chunk;
        bool lt = (pos < lo + len) && (valat(b32, sh, n, pos) < t);
        int k = __popc(__ballot_sync(0xffffffffu, lt));
        if (k == 0) {
            len = 1;
        } else {
            int nl = lo + (k - 1) * chunk + 1;
            int nh = min(lo + k * chunk + 1, lo + len);
            len = nh - nl;
            lo = nl;
        }
    }
    bool lt = (lane < len) && (valat(b32, sh, n, lo + lane) < t);
    return lo + __popc(__ballot_sync(0xffffffffu, lt));
}

__device__ __forceinline__ void acc(float4& s, float4& q, const float4 v)
{
    s.x += v.x; s.y += v.y; s.z += v.z; s.w += v.w;
    q.x += v.x * v.x; q.y += v.y * v.y;
    q.z += v.z * v.z; q.w += v.w * v.w;
}

__global__ __launch_bounds__(TPB, 2) void graphnorm_kernel(
    const float4* __restrict__ x4,
    const int*    __restrict__ b32,
    const float*  __restrict__ weight,
    const float*  __restrict__ bias,
    float4*       __restrict__ out4,
    int n)
{
    __shared__ float4 red_s[RG][D4];
    __shared__ float4 red_q[RG][D4];
    __shared__ float4 sc_s[D4];
    __shared__ float4 sh_s[D4];
    __shared__ int bounds[2];

    const int g    = blockIdx.x;
    const int tid  = threadIdx.x;
    const int c4   = tid & (D4 - 1);   // float4 column
    const int rg   = tid >> 5;         // row group / warp id
    const int lane = tid & 31;

    // ---- Segment boundaries: warp 0 -> lower_bound(g), warp 1 ->
    //      lower_bound(g+1), galloping from the statistical estimate.
    //      Runtime dtype detection: int64 (LE) => odd words near the end
    //      are high words of values < 4096 -> all zero. ----
    if (rg < 2) {
        int probe = b32[n - 1] | b32[n - 3] | b32[n - 5] | b32[n - 7];
        int sh = (probe == 0) ? 1 : 0;
        int res = warp_lb_est(b32, sh, n, g + rg, lane);
        if (lane == 0) bounds[rg] = res;
    }
    __syncthreads();
    const int start = bounds[0];
    const int end   = bounds[1];
    const int cnt   = end - start;

    // ---- Pass 1: per-column sum / sumsq (unroll x4: 4 independent
    //      LDG.128 per warp in flight) ----
    float4 s = make_float4(0.f, 0.f, 0.f, 0.f);
    float4 q = make_float4(0.f, 0.f, 0.f, 0.f);
    int r = start + rg;
    for (; r + 3 * RG < end; r += 4 * RG) {
        float4 v0 = x4[(r         ) * D4 + c4];
        float4 v1 = x4[(r +     RG) * D4 + c4];
        float4 v2 = x4[(r + 2 * RG) * D4 + c4];
        float4 v3 = x4[(r + 3 * RG) * D4 + c4];
        acc(s, q, v0);
        acc(s, q, v1);
        acc(s, q, v2);
        acc(s, q, v3);
    }
    for (; r < end; r += RG) {
        float4 v = x4[r * D4 + c4];
        acc(s, q, v);
    }
    red_s[rg][c4] = s;
    red_q[rg][c4] = q;
    __syncthreads();

    // ---- Flat parallel reduction + fold into scale/shift.
    //      128 threads, one scalar column each: 16 conflict-free LDS per
    //      sum, fully pipelined. ----
    if (tid < DHID) {
        const float* ps = reinterpret_cast<const float*>(red_s);
        const float* pq = reinterpret_cast<const float*>(red_q);
        float S = 0.f, Q = 0.f;
        #pragma unroll
        for (int k = 0; k < RG; ++k) {
            S += ps[k * DHID + tid];
            Q += pq[k * DHID + tid];
        }
        float w = weight[tid];
        float b = bias[tid];
        float sc, sh;
        if (cnt > 1) {
            float inv_n = 1.0f / (float)cnt;
            float m = S * inv_n;
            float v = Q * inv_n - m * m;
            sc = w * rsqrtf(v + EPSV);
            sh = b - m * sc;
        } else {
            // cnt <= 1: reference leaves mean=0, var=1
            sc = w * rsqrtf(1.0f + EPSV);
            sh = b;
        }
        reinterpret_cast<float*>(sc_s)[tid] = sc;
        reinterpret_cast<float*>(sh_s)[tid] = sh;
    }
    __syncthreads();

    // ---- Pass 2: normalize (unroll x2, hoisted sc/sh). x re-read hits L2;
    //      streaming stores keep the output from evicting x segments. ----
    const float4 sc = sc_s[c4];
    const float4 sh = sh_s[c4];
    const int jend = end * D4;
    int j = start * D4 + tid;
    for (; j + TPB < jend; j += 2 * TPB) {
        float4 v0 = x4[j];
        float4 v1 = x4[j + TPB];
        float4 o0, o1;
        o0.x = v0.x * sc.x + sh.x; o0.y = v0.y * sc.y + sh.y;
        o0.z = v0.z * sc.z + sh.z; o0.w = v0.w * sc.w + sh.w;
        o1.x = v1.x * sc.x + sh.x; o1.y = v1.y * sc.y + sh.y;
        o1.z = v1.z * sc.z + sh.z; o1.w = v1.w * sc.w + sh.w;
        __stcs(&out4[j      ], o0);
        __stcs(&out4[j + TPB], o1);
    }
    if (j < jend) {
        float4 v = x4[j];
        float4 o;
        o.x = v.x * sc.x + sh.x;
        o.y = v.y * sc.y + sh.y;
        o.z = v.z * sc.z + sh.z;
        o.w = v.w * sc.w + sh.w;
        __stcs(&out4[j], o);
    }
}

extern "C" void kernel_launch(void* const* d_in, const int* in_sizes, int n_in,
                              void* d_out, int out_size)
{
    const float* x      = (const float*)d_in[0];
    const int*   batch  = (const int*)d_in[1];   // int32 or int64; detected on device
    const float* weight = (const float*)d_in[2];
    const float* bias   = (const float*)d_in[3];
    float*       out    = (float*)d_out;

    int n = in_sizes[1];  // number of nodes

    graphnorm_kernel<<<NUM_G, TPB>>>(
        reinterpret_cast<const float4*>(x), batch, weight, bias,
        reinterpret_cast<float4*>(out), n);
}

// round 17
// speedup vs baseline: 1.0721x; 1.0721x over previous
#include <cuda_runtime.h>

#define NUM_G 4096
#define D4    32          // 128 floats = 32 float4 per row
#define DHID  128
#define TPB   512
#define RG    16          // row groups in pass 1 (TPB / 32)
#define EPSV  1e-5f

__device__ int g_seg_off[NUM_G + 1];

// Vectorized scan-based offsets: each thread owns 16 consecutive positions
// i0..i0+15 of the virtual sequence val(-1)=-1, val(i)=batch[i] (i<n),
// val(n)=NUM_G, and writes g_seg_off[g]=i for every boundary it owns.
// Runtime dtype detection: if batch is int64 (LE), odd 32-bit words near the
// end are high words of values < 4096 -> all zero. If int32, tail ~4095.
__global__ void offsets_kernel(const int* __restrict__ b32, int n)
{
    // PDL: allow the dependent graphnorm grid to begin launching now.
    cudaTriggerProgrammaticLaunchCompletion();

    int t  = blockIdx.x * blockDim.x + threadIdx.x;
    int i0 = t * 16;
    if (i0 > n) return;
    int probe = b32[n - 1] | b32[n - 3] | b32[n - 5] | b32[n - 7];
    int sh = (probe == 0) ? 1 : 0;   // 1 => int64, element i at word (i << 1)

    int prev = (i0 > 0) ? b32[(long long)(i0 - 1) << sh] : -1;

    int v[16];
    if (i0 + 15 < n) {
        if (sh == 0) {
            #pragma unroll
            for (int c = 0; c < 4; ++c) {
                int4 a = *reinterpret_cast<const int4*>(b32 + i0 + 4 * c);
                v[4 * c + 0] = a.x; v[4 * c + 1] = a.y;
                v[4 * c + 2] = a.z; v[4 * c + 3] = a.w;
            }
        } else {
            #pragma unroll
            for (int c = 0; c < 8; ++c) {
                int4 a = *reinterpret_cast<const int4*>(b32 + 2 * i0 + 4 * c);
                v[2 * c + 0] = a.x;   // low words of two int64 elements
                v[2 * c + 1] = a.z;
            }
        }
    } else {
        #pragma unroll
        for (int j = 0; j < 16; ++j)
            v[j] = (i0 + j < n) ? b32[(long long)(i0 + j) << sh] : NUM_G;
    }

    #pragma unroll
    for (int j = 0; j < 16; ++j) {
        int cur = v[j];
        for (int g = prev + 1; g <= cur; ++g)
            g_seg_off[g] = i0 + j;
        prev = cur;
    }
}

__device__ __forceinline__ void acc(float4& s, float4& q, const float4 v)
{
    s.x += v.x; s.y += v.y; s.z += v.z; s.w += v.w;
    q.x += v.x * v.x; q.y += v.y * v.y;
    q.z += v.z * v.z; q.w += v.w * v.w;
}

__global__ __launch_bounds__(TPB, 2) void graphnorm_kernel(
    const float4* __restrict__ x4,
    const float*  __restrict__ weight,
    const float*  __restrict__ bias,
    float4*       __restrict__ out4)
{
    __shared__ float4 red_s[RG][D4];
    __shared__ float4 red_q[RG][D4];
    __shared__ float4 sc_s[D4];
    __shared__ float4 sh_s[D4];

    const int g   = blockIdx.x;
    const int tid = threadIdx.x;
    const int c4  = tid & (D4 - 1);   // float4 column
    const int rg  = tid >> 5;         // row group 0..15

    // PDL: this grid was allowed to launch while offsets_kernel still runs.
    // Block here until offsets_kernel has completed and its writes to
    // g_seg_off are visible.
    cudaGridDependencySynchronize();

    const int start = g_seg_off[g];
    const int end   = g_seg_off[g + 1];
    const int cnt   = end - start;

    // ---- Pass 1: per-column sum / sumsq (unroll x4: 4 independent
    //      LDG.128 per warp in flight) ----
    float4 s = make_float4(0.f, 0.f, 0.f, 0.f);
    float4 q = make_float4(0.f, 0.f, 0.f, 0.f);
    int r = start + rg;
    for (; r + 3 * RG < end; r += 4 * RG) {
        float4 v0 = x4[(r         ) * D4 + c4];
        float4 v1 = x4[(r +     RG) * D4 + c4];
        float4 v2 = x4[(r + 2 * RG) * D4 + c4];
        float4 v3 = x4[(r + 3 * RG) * D4 + c4];
        acc(s, q, v0);
        acc(s, q, v1);
        acc(s, q, v2);
        acc(s, q, v3);
    }
    for (; r < end; r += RG) {
        float4 v = x4[r * D4 + c4];
        acc(s, q, v);
    }
    red_s[rg][c4] = s;
    red_q[rg][c4] = q;
    __syncthreads();

    // ---- Flat parallel reduction + fold into scale/shift.
    //      128 threads, one scalar column each: 16 conflict-free LDS per
    //      sum, fully pipelined. 2 barriers total. ----
    if (tid < DHID) {
        const float* ps = reinterpret_cast<const float*>(red_s);
        const float* pq = reinterpret_cast<const float*>(red_q);
        float S = 0.f, Q = 0.f;
        #pragma unroll
        for (int k = 0; k < RG; ++k) {
            S += ps[k * DHID + tid];
            Q += pq[k * DHID + tid];
        }
        float w = weight[tid];
        float b = bias[tid];
        float sc, sh;
        if (cnt > 1) {
            float inv_n = 1.0f / (float)cnt;
            float m = S * inv_n;
            float v = Q * inv_n - m * m;
            sc = w * rsqrtf(v + EPSV);
            sh = b - m * sc;
        } else {
            // cnt <= 1: reference leaves mean=0, var=1
            sc = w * rsqrtf(1.0f + EPSV);
            sh = b;
        }
        reinterpret_cast<float*>(sc_s)[tid] = sc;
        reinterpret_cast<float*>(sh_s)[tid] = sh;
    }
    __syncthreads();

    // ---- Pass 2: normalize (unroll x2, hoisted sc/sh). x re-read hits L2;
    //      streaming stores keep the output from evicting x segments. ----
    const float4 sc = sc_s[c4];
    const float4 sh = sh_s[c4];
    const int jend = end * D4;
    int j = start * D4 + tid;
    for (; j + TPB < jend; j += 2 * TPB) {
        float4 v0 = x4[j];
        float4 v1 = x4[j + TPB];
        float4 o0, o1;
        o0.x = v0.x * sc.x + sh.x; o0.y = v0.y * sc.y + sh.y;
        o0.z = v0.z * sc.z + sh.z; o0.w = v0.w * sc.w + sh.w;
        o1.x = v1.x * sc.x + sh.x; o1.y = v1.y * sc.y + sh.y;
        o1.z = v1.z * sc.z + sh.z; o1.w = v1.w * sc.w + sh.w;
        __stcs(&out4[j      ], o0);
        __stcs(&out4[j + TPB], o1);
    }
    if (j < jend) {
        float4 v = x4[j];
        float4 o;
        o.x = v.x * sc.x + sh.x;
        o.y = v.y * sc.y + sh.y;
        o.z = v.z * sc.z + sh.z;
        o.w = v.w * sc.w + sh.w;
        __stcs(&out4[j], o);
    }
}

extern "C" void kernel_launch(void* const* d_in, const int* in_sizes, int n_in,
                              void* d_out, int out_size)
{
    const float* x      = (const float*)d_in[0];
    const int*   batch  = (const int*)d_in[1];   // int32 or int64; detected on device
    const float* weight = (const float*)d_in[2];
    const float* bias   = (const float*)d_in[3];
    float*       out    = (float*)d_out;

    int n = in_sizes[1];  // number of nodes

    int nthreads = n / 16 + 1;                  // one thread per 16 boundary slots
    offsets_kernel<<<(nthreads + 255) / 256, 256>>>(batch, n);

    // Launch graphnorm with Programmatic Dependent Launch so it can begin
    // (and run its prologue) while offsets_kernel drains.
    cudaLaunchConfig_t cfg = {};
    cfg.gridDim  = dim3(NUM_G);
    cfg.blockDim = dim3(TPB);
    cfg.dynamicSmemBytes = 0;
    cfg.stream = 0;
    cudaLaunchAttribute attrs[1];
    attrs[0].id = cudaLaunchAttributeProgrammaticStreamSerialization;
    attrs[0].val.programmaticStreamSerializationAllowed = 1;
    cfg.attrs = attrs;
    cfg.numAttrs = 1;
    cudaLaunchKernelEx(&cfg, graphnorm_kernel,
                       reinterpret_cast<const float4*>(x), weight, bias,
                       reinterpret_cast<float4*>(out));
}